// round 4
// baseline (speedup 1.0000x reference)
#include <cuda_runtime.h>

#define NN   50000
#define NE   800000
#define H    256
#define NL   3
#define NIDX 8192   // N_PAIRS * 2

// ---------------- scratch (static device globals; no allocation) -------------
__device__ float g_h[(size_t)NN * H];     // 51.2 MB  (post-conv features)
__device__ float g_x[(size_t)NN * H];     // 51.2 MB  (aggregated features)
__device__ int   g_deg[NN];
__device__ int   g_fill[NN];
__device__ int   g_start[NN];             // exclusive CSR row start
__device__ int   g_csr[NE];               // src node per dst-sorted slot
__device__ float g_W0[NL * H * H];        // f0_w @ conv_w
__device__ float g_W1[NL * H * H];        // f1_w @ conv_w
__device__ float g_B0[NL * H];            // f0_b @ conv_w + conv_b
__device__ float g_B1[NL * H];            // f1_b @ conv_w + conv_b

// ---------------- CSR construction ------------------------------------------
__global__ void k_zero() {
    int i = blockIdx.x * blockDim.x + threadIdx.x;
    if (i < NN) { g_deg[i] = 0; g_fill[i] = 0; }
}

__global__ void k_hist(const int* __restrict__ dst) {
    int e = blockIdx.x * blockDim.x + threadIdx.x;
    if (e < NE) atomicAdd(&g_deg[dst[e]], 1);
}

// single-block exclusive scan of g_deg -> g_start (50000 elems, 49 chunks)
__global__ void k_scan() {
    __shared__ int s1[1024];
    __shared__ int s2[1024];
    int run = 0;
    int t = threadIdx.x;
    for (int base = 0; base < NN; base += 1024) {
        int i = base + t;
        int v = (i < NN) ? g_deg[i] : 0;
        s1[t] = v;
        __syncthreads();
        int* a = s1; int* b = s2;
        #pragma unroll
        for (int off = 1; off < 1024; off <<= 1) {
            int x = a[t];
            if (t >= off) x += a[t - off];
            b[t] = x;
            __syncthreads();
            int* tmp = a; a = b; b = tmp;
        }
        int incl = a[t];
        if (i < NN) g_start[i] = run + incl - v;
        run += a[1023];
        __syncthreads();
    }
}

__global__ void k_scatter(const int* __restrict__ src, const int* __restrict__ dst) {
    int e = blockIdx.x * blockDim.x + threadIdx.x;
    if (e < NE) {
        int d = dst[e];
        int slot = g_start[d] + atomicAdd(&g_fill[d], 1);
        g_csr[slot] = src[e];
    }
}

// ---------------- weight folding:  W = A @ conv_w,  b' = b @ conv_w + conv_b -
__global__ void k_fusew(const float* __restrict__ f0w, const float* __restrict__ f1w,
                        const float* __restrict__ convw) {
    int l = blockIdx.y, which = blockIdx.z;
    const float* A = (which ? f1w : f0w) + (size_t)l * H * H;
    const float* B = convw + (size_t)l * H * H;
    float* C = (which ? g_W1 : g_W0) + (size_t)l * H * H;
    int i = blockIdx.x, j = threadIdx.x;
    float acc = 0.f;
    #pragma unroll 8
    for (int k = 0; k < H; k++) acc += A[i * H + k] * B[k * H + j];
    C[i * H + j] = acc;
}

__global__ void k_fuseb(const float* __restrict__ f0b, const float* __restrict__ f1b,
                        const float* __restrict__ convw, const float* __restrict__ convb) {
    int l = blockIdx.y, which = blockIdx.z;
    const float* bb = (which ? f1b : f0b) + l * H;
    const float* B  = convw + (size_t)l * H * H;
    float* out = (which ? g_B1 : g_B0) + l * H;
    int j = threadIdx.x;
    float acc = convb[l * H + j];
    #pragma unroll 8
    for (int k = 0; k < H; k++) acc += bb[k] * B[k * H + j];
    out[j] = acc;
}

// ---------------- main GEMM: C[M,256] = A[M,256] @ W[256,256] + bias ---------
// BM=128 BN=64 BK=16, 256 threads, 8x4 per thread
__global__ __launch_bounds__(256) void k_gemm(const float* __restrict__ A,
                                              const float* __restrict__ W,
                                              const float* __restrict__ bias,
                                              float* __restrict__ C, int M) {
    __shared__ float As[16][128];
    __shared__ float Bs[16][64];
    const int bm = blockIdx.x * 128;
    const int bn = blockIdx.y * 64;
    const int tid = threadIdx.x;
    const int tx = tid & 15;
    const int ty = tid >> 4;
    const int r   = tid >> 1;           // A-tile row this thread loads
    const int kcb = (tid & 1) * 8;      // A-tile k base
    const int brow = tid >> 4;          // B-tile row
    const int bcol = (tid & 15) << 2;   // B-tile col

    float acc[8][4];
    #pragma unroll
    for (int i = 0; i < 8; i++)
        #pragma unroll
        for (int j = 0; j < 4; j++) acc[i][j] = 0.f;

    for (int k0 = 0; k0 < H; k0 += 16) {
        #pragma unroll
        for (int u = 0; u < 2; u++) {
            int kc = kcb + u * 4;
            int row = bm + r;
            float4 v = make_float4(0.f, 0.f, 0.f, 0.f);
            if (row < M) v = *(const float4*)(A + (size_t)row * H + k0 + kc);
            As[kc + 0][r] = v.x; As[kc + 1][r] = v.y;
            As[kc + 2][r] = v.z; As[kc + 3][r] = v.w;
        }
        *(float4*)&Bs[brow][bcol] = *(const float4*)(W + (size_t)(k0 + brow) * H + bn + bcol);
        __syncthreads();
        #pragma unroll
        for (int k = 0; k < 16; k++) {
            float a[8], b[4];
            *(float4*)&a[0] = *(float4*)&As[k][ty * 8];
            *(float4*)&a[4] = *(float4*)&As[k][ty * 8 + 4];
            *(float4*)&b[0] = *(float4*)&Bs[k][tx * 4];
            #pragma unroll
            for (int i = 0; i < 8; i++)
                #pragma unroll
                for (int j = 0; j < 4; j++)
                    acc[i][j] += a[i] * b[j];
        }
        __syncthreads();
    }
    float4 bv = *(const float4*)(bias + bn + tx * 4);
    #pragma unroll
    for (int i = 0; i < 8; i++) {
        int row = bm + ty * 8 + i;
        if (row < M) {
            float4 o;
            o.x = acc[i][0] + bv.x; o.y = acc[i][1] + bv.y;
            o.z = acc[i][2] + bv.z; o.w = acc[i][3] + bv.w;
            *(float4*)(C + (size_t)row * H + bn + tx * 4) = o;
        }
    }
}

// ---- gather/scatter GEMM for the labeled rows: C[rows[m]] = A[rows[m]]@W + b
__global__ __launch_bounds__(256) void k_gemm_idx(const float* __restrict__ A,
                                                  const float* __restrict__ W,
                                                  const float* __restrict__ bias,
                                                  float* __restrict__ C,
                                                  const int* __restrict__ rows, int M) {
    __shared__ float As[16][128];
    __shared__ float Bs[16][64];
    const int bm = blockIdx.x * 128;
    const int bn = blockIdx.y * 64;
    const int tid = threadIdx.x;
    const int tx = tid & 15;
    const int ty = tid >> 4;
    const int r   = tid >> 1;
    const int kcb = (tid & 1) * 8;
    const int brow = tid >> 4;
    const int bcol = (tid & 15) << 2;

    int arow = (bm + r < M) ? rows[bm + r] : 0;

    float acc[8][4];
    #pragma unroll
    for (int i = 0; i < 8; i++)
        #pragma unroll
        for (int j = 0; j < 4; j++) acc[i][j] = 0.f;

    for (int k0 = 0; k0 < H; k0 += 16) {
        #pragma unroll
        for (int u = 0; u < 2; u++) {
            int kc = kcb + u * 4;
            float4 v = make_float4(0.f, 0.f, 0.f, 0.f);
            if (bm + r < M) v = *(const float4*)(A + (size_t)arow * H + k0 + kc);
            As[kc + 0][r] = v.x; As[kc + 1][r] = v.y;
            As[kc + 2][r] = v.z; As[kc + 3][r] = v.w;
        }
        *(float4*)&Bs[brow][bcol] = *(const float4*)(W + (size_t)(k0 + brow) * H + bn + bcol);
        __syncthreads();
        #pragma unroll
        for (int k = 0; k < 16; k++) {
            float a[8], b[4];
            *(float4*)&a[0] = *(float4*)&As[k][ty * 8];
            *(float4*)&a[4] = *(float4*)&As[k][ty * 8 + 4];
            *(float4*)&b[0] = *(float4*)&Bs[k][tx * 4];
            #pragma unroll
            for (int i = 0; i < 8; i++)
                #pragma unroll
                for (int j = 0; j < 4; j++)
                    acc[i][j] += a[i] * b[j];
        }
        __syncthreads();
    }
    float4 bv = *(const float4*)(bias + bn + tx * 4);
    #pragma unroll
    for (int i = 0; i < 8; i++) {
        int m = bm + ty * 8 + i;
        if (m < M) {
            int crow = rows[m];
            float4 o;
            o.x = acc[i][0] + bv.x; o.y = acc[i][1] + bv.y;
            o.z = acc[i][2] + bv.z; o.w = acc[i][3] + bv.w;
            *(float4*)(C + (size_t)crow * H + bn + tx * 4) = o;
        }
    }
}

// ---------------- aggregation: x[v] = sum over in-edges of h[src] ------------
__global__ __launch_bounds__(256) void k_aggr() {
    int w = (blockIdx.x * blockDim.x + threadIdx.x) >> 5;
    int lane = threadIdx.x & 31;
    if (w >= NN) return;
    int s = g_start[w];
    int e = s + g_deg[w];
    const float4* __restrict__ h4 = (const float4*)g_h;
    float4 a0 = make_float4(0.f, 0.f, 0.f, 0.f);
    float4 a1 = make_float4(0.f, 0.f, 0.f, 0.f);
    #pragma unroll 4
    for (int i = s; i < e; i++) {
        int src = __ldg(&g_csr[i]);
        float4 v0 = h4[(size_t)src * 64 + lane];
        float4 v1 = h4[(size_t)src * 64 + 32 + lane];
        a0.x += v0.x; a0.y += v0.y; a0.z += v0.z; a0.w += v0.w;
        a1.x += v1.x; a1.y += v1.y; a1.z += v1.z; a1.w += v1.w;
    }
    float4* x4 = (float4*)g_x;
    x4[(size_t)w * 64 + lane] = a0;
    x4[(size_t)w * 64 + 32 + lane] = a1;
}

// ---------------- final gather: out[r] = x[pos[r]] ---------------------------
__global__ void k_out(const int* __restrict__ pos, float* __restrict__ out) {
    int rr = blockIdx.x;           // 0..8191
    int t = threadIdx.x;           // 0..63 float4 lanes
    int node = pos[rr];
    ((float4*)out)[(size_t)rr * 64 + t] = ((const float4*)g_x)[(size_t)node * 64 + t];
}

// ---------------- launch -----------------------------------------------------
extern "C" void kernel_launch(void* const* d_in, const int* in_sizes, int n_in,
                              void* d_out, int out_size) {
    const float* x     = (const float*)d_in[0];
    const float* f0w   = (const float*)d_in[1];
    const float* f0b   = (const float*)d_in[2];
    const float* f1w   = (const float*)d_in[3];
    const float* f1b   = (const float*)d_in[4];
    const float* convw = (const float*)d_in[5];
    const float* convb = (const float*)d_in[6];
    const int*   esrc  = (const int*)d_in[7];
    const int*   edst  = (const int*)d_in[8];
    const int*   pos   = (const int*)d_in[9];
    float* out = (float*)d_out;

    static float *hbuf = nullptr, *xbuf = nullptr, *W0, *W1, *B0, *B1;
    if (!hbuf) {
        cudaGetSymbolAddress((void**)&hbuf, g_h);
        cudaGetSymbolAddress((void**)&xbuf, g_x);
        cudaGetSymbolAddress((void**)&W0, g_W0);
        cudaGetSymbolAddress((void**)&W1, g_W1);
        cudaGetSymbolAddress((void**)&B0, g_B0);
        cudaGetSymbolAddress((void**)&B1, g_B1);
    }

    // CSR build
    k_zero<<<(NN + 255) / 256, 256>>>();
    k_hist<<<(NE + 255) / 256, 256>>>(edst);
    k_scan<<<1, 1024>>>();
    k_scatter<<<(NE + 255) / 256, 256>>>(esrc, edst);

    // fold (f0,f1) through conv
    k_fusew<<<dim3(H, NL, 2), H>>>(f0w, f1w, convw);
    k_fuseb<<<dim3(1, NL, 2), H>>>(f0b, f1b, convw, convb);

    const float* xin = x;
    for (int l = 0; l < NL; l++) {
        k_gemm<<<dim3((NN + 127) / 128, H / 64), 256>>>(
            xin, W0 + (size_t)l * H * H, B0 + l * H, hbuf, NN);
        k_gemm_idx<<<dim3(NIDX / 128, H / 64), 256>>>(
            xin, W1 + (size_t)l * H * H, B1 + l * H, hbuf, pos, NIDX);
        k_aggr<<<(NN * 32 + 255) / 256, 256>>>();
        xin = xbuf;
    }
    k_out<<<NIDX, 64>>>(pos, out);
}